// round 17
// baseline (speedup 1.0000x reference)
#include <cuda_runtime.h>
#include <cstdint>

// RaySamples volume rendering: 256-bit loads (LDG.256), 8 samples/thread.
//
// All structural variants pin at ~18us kernel time => LTS-path bound.
// Halve the request-side load instruction/wavefront count with
// ld.global.L2::evict_last.v8.b32 (sm_103 256-bit global load; the bare
// evict_last modifier is only legal on this shape, and gives input L2
// residency across graph replays for free).
//
// Layout: 2 rays per warp; half-warp (16 threads) covers one ray's 128
// samples, 8 consecutive samples per thread (32B = one LDG.256).
// Exclusive scan: per-thread sum -> width-16 shuffle scan -> in-thread
// serial T chain (T_{i+1} = T_i * e_i), W_i = T_i - T_{i+1}.
// Output: d_out[0:N*K] = weights, d_out[N*K:2N*K] = transmittance.

static constexpr int N_RAYS    = 65536;
static constexpr int K_SAMPLES = 128;

struct F8 { float v[8]; };

__device__ __forceinline__ F8 ldg256_evict_last(const float* p) {
    F8 r;
    asm volatile("ld.global.L2::evict_last.v8.b32 {%0,%1,%2,%3,%4,%5,%6,%7}, [%8];"
                 : "=f"(r.v[0]), "=f"(r.v[1]), "=f"(r.v[2]), "=f"(r.v[3]),
                   "=f"(r.v[4]), "=f"(r.v[5]), "=f"(r.v[6]), "=f"(r.v[7])
                 : "l"(p));
    return r;
}

__device__ __forceinline__ void st_cs4(float* p, float a, float b, float c, float d) {
    asm volatile("st.global.cs.v4.f32 [%0], {%1,%2,%3,%4};"
                 :: "l"(p), "f"(a), "f"(b), "f"(c), "f"(d)
                 : "memory");
}

__global__ void __launch_bounds__(256) ray_samples_kernel(
    const float* __restrict__ dens,
    const float* __restrict__ delt,
    float* __restrict__ w_out,
    float* __restrict__ t_out)
{
    const int tid  = blockIdx.x * blockDim.x + threadIdx.x;
    const int lane = threadIdx.x & 31;
    const int sub  = lane & 15;              // position within half-warp (segment)

    // Each thread owns 8 consecutive samples; 16 threads = 1 ray.
    // Global float offset: tid * 8 (rays are laid out contiguously).
    const int base = tid * 8;

    const F8 d = ldg256_evict_last(&dens[base]);
    const F8 l = ldg256_evict_last(&delt[base]);

    float dd[8];
    #pragma unroll
    for (int i = 0; i < 8; ++i) dd[i] = d.v[i] * l.v[i];

    const float local_sum = ((dd[0] + dd[1]) + (dd[2] + dd[3]))
                          + ((dd[4] + dd[5]) + (dd[6] + dd[7]));

    // Width-16 inclusive scan within each half-warp segment.
    float scan = local_sum;
    #pragma unroll
    for (int off = 1; off < 16; off <<= 1) {
        float v = __shfl_up_sync(0xffffffffu, scan, off);
        if (sub >= off) scan += v;
    }
    const float excl = scan - local_sum;     // exclusive optical depth at sample 8*sub

    // e_i = exp(-dd_i); T chain; W_i = T_i - T_{i+1}. 9 MUFU / 8 samples.
    float e[8];
    #pragma unroll
    for (int i = 0; i < 8; ++i) e[i] = __expf(-dd[i]);

    float t[9];
    t[0] = __expf(-excl);
    #pragma unroll
    for (int i = 0; i < 8; ++i) t[i + 1] = t[i] * e[i];

    st_cs4(&w_out[base],     t[0] - t[1], t[1] - t[2], t[2] - t[3], t[3] - t[4]);
    st_cs4(&w_out[base + 4], t[4] - t[5], t[5] - t[6], t[6] - t[7], t[7] - t[8]);
    st_cs4(&t_out[base],     t[0], t[1], t[2], t[3]);
    st_cs4(&t_out[base + 4], t[4], t[5], t[6], t[7]);
}

extern "C" void kernel_launch(void* const* d_in, const int* in_sizes, int n_in,
                              void* d_out, int out_size)
{
    const float* dens = (const float*)d_in[0];   // densities [N, K, 1] fp32
    const float* delt = (const float*)d_in[1];   // deltas    [N, K, 1] fp32
    float* out = (float*)d_out;

    const int total_elems = N_RAYS * K_SAMPLES;  // 8,388,608
    float* w_out = out;                          // weights
    float* t_out = out + total_elems;            // transmittance

    const int threads = 256;
    const int total_threads = total_elems / 8;   // 1,048,576
    const int blocks = total_threads / threads;  // 4096
    ray_samples_kernel<<<blocks, threads>>>(dens, delt, w_out, t_out);
}